// round 16
// baseline (speedup 1.0000x reference)
#include <cuda_runtime.h>

// Problem dims
#define B_  2048
#define M_  128
#define D_  512
#define H_  512
#define KU_ 1024

// GEMM tiling: 128x64 tile, BK=16, 256 threads, 8Mx4N micro-tile, M-packed f32x2
#define BM 128
#define BN 64
#define BK 16
#define AS_LD (BM + 4)   // 132
#define WS_LD (BN + 4)   // 68

// Worker streaming: 4 x 8KB smem ring, issue depth 3
#define CHUNK_BYTES 8192
#define CHUNK_F4    512          // float4 per chunk (4 nodes x 128)
#define CHUNKS_PER_ROW 32        // 256KB row / 8KB
#define ROWS_PER_WORKER 32       // 4096 row-jobs / 128 workers
#define NG_CHUNKS (ROWS_PER_WORKER * CHUNKS_PER_ROW)   // 1024

typedef unsigned long long u64;
typedef unsigned int u32;

// Scratch + flags (device globals — no allocation allowed)
__device__ float g_mi[B_ * H_];
__device__ float g_mt[B_ * H_];
__device__ float g_u [B_ * H_];
__device__ u32   g_mcnt[16];
__device__ u32   g_ucnt[16];

// ---------------------------------------------------------------------------
__device__ __forceinline__ u32 ld_acq(const u32* p) {
    u32 v; asm volatile("ld.acquire.gpu.global.u32 %0, [%1];" : "=r"(v) : "l"(p)); return v;
}
__device__ __forceinline__ void red_rel(u32* p) {
    asm volatile("red.release.gpu.global.add.u32 [%0], 1;" :: "l"(p) : "memory");
}
__device__ __forceinline__ void fma2(u64& d, u64 a, u64 b) {
    asm volatile("fma.rn.f32x2 %0, %1, %2, %0;" : "+l"(d) : "l"(a), "l"(b));
}
__device__ __forceinline__ u64 pack2(float x) {
    u64 r; asm("mov.b64 %0, {%1, %1};" : "=l"(r) : "f"(x)); return r;
}
__device__ __forceinline__ float2 unpk(u64 v) {
    float2 r; asm("mov.b64 {%0,%1}, %2;" : "=f"(r.x), "=f"(r.y) : "l"(v)); return r;
}
__device__ __forceinline__ u32 smem_u32(const void* p) {
    return (u32)__cvta_generic_to_shared(p);
}
__device__ __forceinline__ void mbar_init(u32 mbar, u32 cnt) {
    asm volatile("mbarrier.init.shared.b64 [%0], %1;" :: "r"(mbar), "r"(cnt) : "memory");
}
__device__ __forceinline__ void mbar_expect_tx(u32 mbar, u32 bytes) {
    asm volatile("mbarrier.arrive.expect_tx.shared.b64 _, [%0], %1;" :: "r"(mbar), "r"(bytes) : "memory");
}
__device__ __forceinline__ void bulk_cp(u32 dst, const void* src, u32 bytes, u32 mbar) {
    asm volatile("cp.async.bulk.shared::cluster.global.mbarrier::complete_tx::bytes [%0], [%1], %2, [%3];"
                 :: "r"(dst), "l"(src), "r"(bytes), "r"(mbar) : "memory");
}
__device__ __forceinline__ void fence_pa() {
    asm volatile("fence.proxy.async.shared::cta;" ::: "memory");
}
__device__ __forceinline__ void mbar_wait(u32 mbar, u32 parity) {
    u32 done;
    asm volatile(
        "{\n\t.reg .pred p;\n\t"
        "mbarrier.try_wait.parity.acquire.cta.shared::cta.b64 p, [%1], %2;\n\t"
        "selp.b32 %0, 1, 0, p;\n\t}"
        : "=r"(done) : "r"(mbar), "r"(parity) : "memory");
    if (!done) {
        asm volatile(
            "{\n\t.reg .pred P1;\n\t"
            "WL_%=:\n\t"
            "mbarrier.try_wait.parity.acquire.cta.shared::cta.b64 P1, [%0], %1, 0x989680;\n\t"
            "@P1 bra.uni WD_%=;\n\t"
            "bra.uni WL_%=;\n\t"
            "WD_%=:\n\t}"
            :: "r"(mbar), "r"(parity) : "memory");
    }
}

// ---------------------------------------------------------------------------
__device__ __forceinline__ void sts_a(float (*As)[AS_LD], const float4& v, int row, int cv) {
    As[cv + 0][row] = v.x; As[cv + 1][row] = v.y;
    As[cv + 2][row] = v.z; As[cv + 3][row] = v.w;
}
__device__ __forceinline__ void sts_w(float (*Ws)[WS_LD], const float4& v, int row, int cv) {
    Ws[cv + 0][row] = v.x; Ws[cv + 1][row] = v.y;
    Ws[cv + 2][row] = v.z; Ws[cv + 3][row] = v.w;
}

// Inner: 8M (4 packed pairs) x 4N per thread.
__device__ __forceinline__ void tile_fma(
    u64 acc[4][4], const float (*As)[AS_LD], const float (*Ws)[WS_LD], int ty, int tx)
{
#pragma unroll
    for (int kk = 0; kk < BK; kk++) {
        const u64* ap = reinterpret_cast<const u64*>(&As[kk][ty * 8]);
        ulonglong2 a01 = *reinterpret_cast<const ulonglong2*>(ap);
        ulonglong2 a23 = *reinterpret_cast<const ulonglong2*>(ap + 2);
        float4 w = *reinterpret_cast<const float4*>(&Ws[kk][tx * 4]);
        u64 a0 = a01.x, a1 = a01.y, a2 = a23.x, a3 = a23.y;
        u64 w0 = pack2(w.x), w1 = pack2(w.y), w2 = pack2(w.z), w3 = pack2(w.w);
        fma2(acc[0][0], a0, w0); fma2(acc[1][0], a1, w0);
        fma2(acc[2][0], a2, w0); fma2(acc[3][0], a3, w0);
        fma2(acc[0][1], a0, w1); fma2(acc[1][1], a1, w1);
        fma2(acc[2][1], a2, w1); fma2(acc[3][1], a3, w1);
        fma2(acc[0][2], a0, w2); fma2(acc[1][2], a1, w2);
        fma2(acc[2][2], a2, w2); fma2(acc[3][2], a3, w2);
        fma2(acc[0][3], a0, w3); fma2(acc[1][3], a1, w3);
        fma2(acc[2][3], a2, w3); fma2(acc[3][3], a3, w3);
    }
}

// Pipelined K=512 phase over smem double buffers.
__device__ __forceinline__ void run_phase(
    u64 acc[4][4],
    const float* __restrict__ A,
    const float* __restrict__ W0, const float* __restrict__ W1,
    float (*As)[BK][AS_LD], float (*Ws)[BK][WS_LD],
    int bm, int bn, int tid, int ty, int tx)
{
    const int r0 = tid >> 2;
    const int cv = (tid & 3) << 2;
    const int NT = H_ / BK;   // 32

    float4 a0, a1, wv;
    {
        a0 = *reinterpret_cast<const float4*>(A + (size_t)(bm + r0) * H_ + cv);
        a1 = *reinterpret_cast<const float4*>(A + (size_t)(bm + r0 + 64) * H_ + cv);
        wv = *reinterpret_cast<const float4*>(W0 + (size_t)(bn + (r0 & 63)) * H_ + cv);
        if (W1) {
            float4 w2 = *reinterpret_cast<const float4*>(W1 + (size_t)(bn + (r0 & 63)) * H_ + cv);
            wv.x += w2.x; wv.y += w2.y; wv.z += w2.z; wv.w += w2.w;
        }
        sts_a(As[0], a0, r0, cv); sts_a(As[0], a1, r0 + 64, cv);
        sts_w(Ws[0], wv, r0 & 63, cv);
    }
    __syncthreads();

    int p = 0;
    for (int t = 0; t < NT; t++) {
        if (t + 1 < NT) {
            int kt = (t + 1) * BK;
            a0 = *reinterpret_cast<const float4*>(A + (size_t)(bm + r0) * H_ + kt + cv);
            a1 = *reinterpret_cast<const float4*>(A + (size_t)(bm + r0 + 64) * H_ + kt + cv);
            wv = *reinterpret_cast<const float4*>(W0 + (size_t)(bn + (r0 & 63)) * H_ + kt + cv);
            if (W1) {
                float4 w2 = *reinterpret_cast<const float4*>(W1 + (size_t)(bn + (r0 & 63)) * H_ + kt + cv);
                wv.x += w2.x; wv.y += w2.y; wv.z += w2.z; wv.w += w2.w;
            }
        }
        tile_fma(acc, As[p], Ws[p], ty, tx);
        if (t + 1 < NT) {
            sts_a(As[p ^ 1], a0, r0, cv); sts_a(As[p ^ 1], a1, r0 + 64, cv);
            sts_w(Ws[p ^ 1], wv, r0 & 63, cv);
        }
        __syncthreads();
        p ^= 1;
    }
}

// ---------------------------------------------------------------------------
__global__ void zero_flags() {
    if (threadIdx.x < 16) { g_mcnt[threadIdx.x] = 0; g_ucnt[threadIdx.x] = 0; }
}

// ---------------------------------------------------------------------------
// Shared-memory union layout (static, 48KB limit):
//   Compute: As[2][16][132] @0 (16896B), Ws[2][16][68] @16896 (8704B) = 25600B
//   Worker:  mbar[4] @0 (32B), redbuf float4[128] @32 (2048B),
//            bufs 4 x 8192B @2080 .. 34848
#define SMEM_BYTES 34848

// grid=256, 256 threads, 2 CTAs/SM -> all 256 co-resident (296 slots).
//   CTAs 0..127   : compute. tile=cid>>3, n-slot=cid&7 (BN=64).
//   CTAs 128..255 : TMA-bulk mean workers. Worker w streams, per tile t,
//                   rows (t, w) and (t, w+128) of the 256-job tile block;
//                   releases g_mcnt[t] after finishing its pair -> tiles
//                   complete progressively in order.
// ---------------------------------------------------------------------------
__global__ void __launch_bounds__(256, 2) fused_all(
    const float* __restrict__ it,  const float* __restrict__ ii,
    const float* __restrict__ btf, const float* __restrict__ bif,
    const float* __restrict__ Wu,  const float* __restrict__ bu,
    const float* __restrict__ Wli, const float* __restrict__ bli,
    const float* __restrict__ Wri, const float* __restrict__ Wlt,
    const float* __restrict__ blt, const float* __restrict__ Wrt,
    float* __restrict__ out)
{
    __shared__ __align__(128) char sm[SMEM_BYTES];

    const int cid = blockIdx.x;
    const int tid = threadIdx.x;

    if (cid >= 128) {
        // ================= TMA-bulk mean workers =================
        const int w = cid - 128;             // 0..127
        u64* mbar_g = reinterpret_cast<u64*>(sm);
        float4* redbuf = reinterpret_cast<float4*>(sm + 32);
        const u32 mb0 = smem_u32(mbar_g);
        const u32 buf0 = smem_u32(sm + 2080);

        if (tid == 0) {
#pragma unroll
            for (int i = 0; i < 4; i++) mbar_init(mb0 + i * 8, 1);
            fence_pa();
        }
        __syncthreads();

        const int col  = tid & 127;          // float4 column
        const int half = tid >> 7;           // nodes half
        const float sc = 1.0f / (float)M_;

        // row base pointer for flat job jj (0..31)
        auto row_base = [&](int jj) -> const float* {
            int t     = jj >> 1;
            int inner = (jj & 1) ? (w + 128) : w;
            int modal = inner >> 7;
            int row   = t * 128 + (inner & 127);
            return (modal ? btf : bif) + (size_t)row * (M_ * H_);
        };
        auto dst_ptr = [&](int jj) -> float* {
            int t     = jj >> 1;
            int inner = (jj & 1) ? (w + 128) : w;
            int modal = inner >> 7;
            int row   = t * 128 + (inner & 127);
            return (modal ? g_mt : g_mi) + (size_t)row * H_;
        };

        // prologue: issue chunks 0,1,2
        if (tid == 0) {
#pragma unroll
            for (int g = 0; g < 3; g++) {
                const float* src = row_base(g >> 5) + (size_t)(g & 31) * (CHUNK_F4 * 4);
                mbar_expect_tx(mb0 + (g & 3) * 8, CHUNK_BYTES);
                bulk_cp(buf0 + (g & 3) * CHUNK_BYTES, src, CHUNK_BYTES, mb0 + (g & 3) * 8);
            }
        }

        int ph[4] = {0, 0, 0, 0};
        float4 acc0 = make_float4(0.f, 0.f, 0.f, 0.f);
        float4 acc1 = make_float4(0.f, 0.f, 0.f, 0.f);

        for (int g = 0; g < NG_CHUNKS; g++) {
            const int b = g & 3;
            // issue chunk g+3 into buffer (g+3)&3 (consumed at iter g-1, synced)
            if (tid == 0 && g + 3 < NG_CHUNKS) {
                int gn = g + 3;
                const float* src = row_base(gn >> 5) + (size_t)(gn & 31) * (CHUNK_F4 * 4);
                fence_pa();
                mbar_expect_tx(mb0 + ((gn & 3)) * 8, CHUNK_BYTES);
                bulk_cp(buf0 + (gn & 3) * CHUNK_BYTES, src, CHUNK_BYTES, mb0 + (gn & 3) * 8);
            }
            // wait current chunk
            mbar_wait(mb0 + b * 8, ph[b]); ph[b] ^= 1;

            // accumulate: chunk holds 4 nodes x 512 floats; this thread sums
            // nodes half*2, half*2+1 at its column
            const float4* bc = reinterpret_cast<const float4*>(sm + 2080 + b * CHUNK_BYTES);
            float4 v0 = bc[(half * 2 + 0) * 128 + col];
            float4 v1 = bc[(half * 2 + 1) * 128 + col];
            acc0.x += v0.x; acc0.y += v0.y; acc0.z += v0.z; acc0.w += v0.w;
            acc1.x += v1.x; acc1.y += v1.y; acc1.z += v1.z; acc1.w += v1.w;

            if ((g & 31) == 31) {
                // finish row jj = g>>5
                float4 s = make_float4(acc0.x + acc1.x, acc0.y + acc1.y,
                                       acc0.z + acc1.z, acc0.w + acc1.w);
                if (half) redbuf[col] = s;
                __syncthreads();
                if (!half) {
                    float4 o = redbuf[col];
                    reinterpret_cast<float4*>(dst_ptr(g >> 5))[col] =
                        make_float4((s.x + o.x) * sc, (s.y + o.y) * sc,
                                    (s.z + o.z) * sc, (s.w + o.w) * sc);
                }
                acc0 = make_float4(0.f, 0.f, 0.f, 0.f);
                acc1 = make_float4(0.f, 0.f, 0.f, 0.f);
                __syncthreads();
                if ((g & 63) == 63) {       // finished both jobs of tile t
                    if (tid == 0) red_rel(&g_mcnt[g >> 6]);
                }
            }
            __syncthreads();
        }
        return;
    }

    // ================= compute CTAs =================
    float (*As)[BK][AS_LD] = reinterpret_cast<float (*)[BK][AS_LD]>(sm);
    float (*Ws)[BK][WS_LD] = reinterpret_cast<float (*)[BK][WS_LD]>(sm + 16896);

    const int tile = cid >> 3;
    const int bm   = tile * BM;
    const int bn   = (cid & 7) * BN;
    const int tx   = tid & 15;
    const int ty   = tid >> 4;
    const int r0   = tid >> 2;
    const int cv   = (tid & 3) << 2;

    // ---- Stage 1: gemm_user tile ----
    {
        u64 acc[4][4];
#pragma unroll
        for (int i = 0; i < 4; i++)
#pragma unroll
            for (int j = 0; j < 4; j++) acc[i][j] = 0ull;

        const int NT = KU_ / BK;   // 64
        float4 a0, a1, wv;
        {
            int kg = cv;
            const float* p0 = (kg < D_) ? (it + (size_t)(bm + r0) * D_ + kg)
                                        : (ii + (size_t)(bm + r0) * D_ + (kg - D_));
            const float* p1 = (kg < D_) ? (it + (size_t)(bm + r0 + 64) * D_ + kg)
                                        : (ii + (size_t)(bm + r0 + 64) * D_ + (kg - D_));
            a0 = *reinterpret_cast<const float4*>(p0);
            a1 = *reinterpret_cast<const float4*>(p1);
            wv = *reinterpret_cast<const float4*>(Wu + (size_t)(bn + (r0 & 63)) * KU_ + cv);
            sts_a(As[0], a0, r0, cv); sts_a(As[0], a1, r0 + 64, cv);
            sts_w(Ws[0], wv, r0 & 63, cv);
        }
        __syncthreads();

        int p = 0;
        for (int t = 0; t < NT; t++) {
            if (t + 1 < NT) {
                int kt = (t + 1) * BK;
                int kg = kt + cv;
                const float* p0 = (kg < D_) ? (it + (size_t)(bm + r0) * D_ + kg)
                                            : (ii + (size_t)(bm + r0) * D_ + (kg - D_));
                const float* p1 = (kg < D_) ? (it + (size_t)(bm + r0 + 64) * D_ + kg)
                                            : (ii + (size_t)(bm + r0 + 64) * D_ + (kg - D_));
                a0 = *reinterpret_cast<const float4*>(p0);
                a1 = *reinterpret_cast<const float4*>(p1);
                wv = *reinterpret_cast<const float4*>(Wu + (size_t)(bn + (r0 & 63)) * KU_ + kt + cv);
            }
            tile_fma(acc, As[p], Ws[p], ty, tx);
            if (t + 1 < NT) {
                sts_a(As[p ^ 1], a0, r0, cv); sts_a(As[p ^ 1], a1, r0 + 64, cv);
                sts_w(Ws[p ^ 1], wv, r0 & 63, cv);
            }
            __syncthreads();
            p ^= 1;
        }

        float4 bb = *reinterpret_cast<const float4*>(bu + bn + tx * 4);
#pragma unroll
        for (int i = 0; i < 4; i++) {
            float2 c0 = unpk(acc[i][0]);
            float2 c1 = unpk(acc[i][1]);
            float2 c2 = unpk(acc[i][2]);
            float2 c3 = unpk(acc[i][3]);
            int r = bm + ty * 8 + 2 * i;
            *reinterpret_cast<float4*>(g_u + (size_t)r * H_ + bn + tx * 4) =
                make_float4(c0.x + bb.x, c1.x + bb.y, c2.x + bb.z, c3.x + bb.w);
            *reinterpret_cast<float4*>(g_u + (size_t)(r + 1) * H_ + bn + tx * 4) =
                make_float4(c0.y + bb.x, c1.y + bb.y, c2.y + bb.z, c3.y + bb.w);
        }
    }
    __syncthreads();
    if (tid == 0) red_rel(&g_ucnt[tile]);

    // ---- Stage 2: wait own tile's g_u slices, phase3 ----
    if (tid == 0) { while (ld_acq(&g_ucnt[tile]) < 8u) __nanosleep(128); }
    __syncthreads();

    u64 acc[4][4];
#pragma unroll
    for (int i = 0; i < 4; i++)
#pragma unroll
        for (int j = 0; j < 4; j++) acc[i][j] = 0ull;

    run_phase(acc, g_u, Wri, Wrt, As, Ws, bm, bn, tid, ty, tx);

    // ---- Stage 3: wait this tile's means, phases mi, mt ----
    if (tid == 0) { while (ld_acq(&g_mcnt[tile]) < 128u) __nanosleep(256); }
    __syncthreads();

    run_phase(acc, g_mi, Wli, (const float*)0, As, Ws, bm, bn, tid, ty, tx);
    run_phase(acc, g_mt, Wlt, (const float*)0, As, Ws, bm, bn, tid, ty, tx);

    // epilogue: + (bli+blt), ReLU
    float4 b1 = *reinterpret_cast<const float4*>(bli + bn + tx * 4);
    float4 b2 = *reinterpret_cast<const float4*>(blt + bn + tx * 4);
    float4 bb = make_float4(b1.x + b2.x, b1.y + b2.y, b1.z + b2.z, b1.w + b2.w);
#pragma unroll
    for (int i = 0; i < 4; i++) {
        float2 c0 = unpk(acc[i][0]);
        float2 c1 = unpk(acc[i][1]);
        float2 c2 = unpk(acc[i][2]);
        float2 c3 = unpk(acc[i][3]);
        int r = bm + ty * 8 + 2 * i;
        *reinterpret_cast<float4*>(out + (size_t)r * H_ + bn + tx * 4) =
            make_float4(fmaxf(c0.x + bb.x, 0.f), fmaxf(c1.x + bb.y, 0.f),
                        fmaxf(c2.x + bb.z, 0.f), fmaxf(c3.x + bb.w, 0.f));
        *reinterpret_cast<float4*>(out + (size_t)(r + 1) * H_ + bn + tx * 4) =
            make_float4(fmaxf(c0.y + bb.x, 0.f), fmaxf(c1.y + bb.y, 0.f),
                        fmaxf(c2.y + bb.z, 0.f), fmaxf(c3.y + bb.w, 0.f));
    }
}

// ---------------------------------------------------------------------------
extern "C" void kernel_launch(void* const* d_in, const int* in_sizes, int n_in,
                              void* d_out, int out_size) {
    (void)in_sizes; (void)n_in; (void)out_size;
    const float* it  = (const float*)d_in[0];
    const float* ii  = (const float*)d_in[1];
    const float* btf = (const float*)d_in[2];
    const float* bif = (const float*)d_in[3];
    const float* Wu  = (const float*)d_in[4];
    const float* bu  = (const float*)d_in[5];
    const float* Wli = (const float*)d_in[6];
    const float* bli = (const float*)d_in[7];
    const float* Wri = (const float*)d_in[8];
    const float* Wlt = (const float*)d_in[9];
    const float* blt = (const float*)d_in[10];
    const float* Wrt = (const float*)d_in[11];
    float* out = (float*)d_out;

    zero_flags<<<1, 32>>>();
    fused_all<<<256, 256>>>(it, ii, btf, bif, Wu, bu, Wli, bli, Wri,
                            Wlt, blt, Wrt, out);
}